// round 11
// baseline (speedup 1.0000x reference)
#include <cuda_runtime.h>
#include <cuda_bf16.h>
#include <cstdint>

// DLRM dot-interaction via BF16 tensor cores with 3-term split (fp32-grade accuracy).
// One sample per 64-thread CTA (2 warps, split-k: 64 dims each).
// SYRK symmetry in the fragment domain: for Z = T*T^T the m16n8k16 A-fragment
// registers are a re-indexing of the 4 B-fragment registers
//   a(mt) = { b(2mt)[0], b(2mt+1)[0], b(2mt)[1], b(2mt+1)[1] },
// so only B fragments (8 split2 per ktile) are loaded/split; A aliases them.
// Only the 6 of 8 m16n8 output tiles intersecting the strict upper triangle are
// computed. Each position: 3 bf16 mmas (ah*bh + ah*bl + al*bh), x = x_hi(trunc
// bf16) + x_lo(residual rn-bf16); dropped al*bl ~ 2^-16.

constexpr int Bt      = 16384;
constexpr int NE      = 26;
constexpr int D       = 128;
constexpr int N       = 27;
constexpr int NPAIR   = N * (N - 1) / 2;   // 351
constexpr int STRF    = 136;               // floats per smem row
constexpr int STR4    = 34;                // float4 per smem row
constexpr int NTHR    = 64;
constexpr int NTILE   = 6;

__device__ __forceinline__ void mma_bf16(float* c,
    uint32_t a0, uint32_t a1, uint32_t a2, uint32_t a3,
    uint32_t b0, uint32_t b1)
{
    asm volatile(
        "mma.sync.aligned.m16n8k16.row.col.f32.bf16.bf16.f32 "
        "{%0,%1,%2,%3}, {%4,%5,%6,%7}, {%8,%9}, {%0,%1,%2,%3};"
        : "+f"(c[0]), "+f"(c[1]), "+f"(c[2]), "+f"(c[3])
        : "r"(a0), "r"(a1), "r"(a2), "r"(a3), "r"(b0), "r"(b1));
}

// Split a float2 into packed bf16 (hi, lo) pairs. hi = truncate-to-bf16 (exact
// top 16 bits, one PRMT); lo = rn-bf16 of the exact fp32 residual.
__device__ __forceinline__ void split2(float2 v, uint32_t& hi, uint32_t& lo)
{
    const uint32_t bx = __float_as_uint(v.x), by = __float_as_uint(v.y);
    hi = __byte_perm(bx, by, 0x7632);        // low16 = v.x_hi, high16 = v.y_hi
    const float lx = v.x - __uint_as_float(bx & 0xFFFF0000u);
    const float ly = v.y - __uint_as_float(by & 0xFFFF0000u);
    __nv_bfloat162 l2 = __floats2bfloat162_rn(lx, ly);   // low = lx
    lo = *reinterpret_cast<uint32_t*>(&l2);
}

__global__ void __launch_bounds__(NTHR)
dot_interaction_kernel(const float* __restrict__ dense,
                       const float* __restrict__ embs,
                       float* __restrict__ out)
{
    __shared__ float S[32 * STRF];                   // 17408 B

    const int tid  = threadIdx.x;
    const int kw   = tid >> 5;                       // k-half: 0 or 1
    const int lane = tid & 31;
    const int g    = lane >> 2;                      // groupID
    const int t4   = lane & 3;                       // thread-in-group
    const int sample = blockIdx.x;

    // ---- Load phase: 64 threads stage T (32x128, rows 27..31 zero) ----
    float4* S4 = reinterpret_cast<float4*>(S);
    const float4* d4 = reinterpret_cast<const float4*>(dense + (size_t)sample * D);
    const float4* e4 = reinterpret_cast<const float4*>(embs + (size_t)sample * NE * D);

    if (tid < 32) S4[tid] = d4[tid];                 // row 0 = dense (32 float4)
    #pragma unroll
    for (int i = tid; i < NE * 32; i += NTHR) {      // rows 1..26 = embs (832 f4)
        const int row = i >> 5, col = i & 31;
        S4[(row + 1) * STR4 + col] = e4[i];
    }
    #pragma unroll
    for (int i = tid; i < 5 * STR4; i += NTHR)       // rows 27..31 = zero
        S4[27 * STR4 + i] = make_float4(0.f, 0.f, 0.f, 0.f);
    __syncthreads();

    // Upper-triangle tile list: e -> (mt, nt)
    constexpr int MT[NTILE] = {0, 0, 0, 0, 1, 1};
    constexpr int NT[NTILE] = {0, 1, 2, 3, 2, 3};

    float acc[NTILE][4];
    #pragma unroll
    for (int e = 0; e < NTILE; e++)
        #pragma unroll
        for (int c = 0; c < 4; c++) acc[e][c] = 0.f;

    const int kbase = kw * 64;                       // this warp's k-half

    #pragma unroll
    for (int kt = 0; kt < 4; kt++) {                 // 4 ktiles of k=16
        const int k0 = kbase + kt * 16;
        const int kc = k0 + 2 * t4;                  // this thread's col pair

        // B fragments only (col-major 16k x 8n, B[k][n] = T[n][k]).
        // A fragments alias these (see header comment).
        uint32_t bh[4][2], bl[4][2];
        #pragma unroll
        for (int nt = 0; nt < 4; nt++) {
            const int n = nt * 8 + g;
            split2(*reinterpret_cast<const float2*>(&S[n * STRF + kc    ]), bh[nt][0], bl[nt][0]);
            split2(*reinterpret_cast<const float2*>(&S[n * STRF + kc + 8]), bh[nt][1], bl[nt][1]);
        }
        // 3-term bf16 on the 6 useful tiles: small terms first, then hi*hi
        #pragma unroll
        for (int e = 0; e < NTILE; e++) {
            float* c = acc[e];
            const int m2 = 2 * MT[e], n = NT[e];
            mma_bf16(c, bl[m2][0], bl[m2+1][0], bl[m2][1], bl[m2+1][1],
                        bh[n][0],  bh[n][1]);
            mma_bf16(c, bh[m2][0], bh[m2+1][0], bh[m2][1], bh[m2+1][1],
                        bl[n][0],  bl[n][1]);
            mma_bf16(c, bh[m2][0], bh[m2+1][0], bh[m2][1], bh[m2+1][1],
                        bh[n][0],  bh[n][1]);
        }
    }

    // ---- Cross-warp reduction via dead tile smem ----
    __syncthreads();                                 // everyone done reading T
    if (kw == 1) {
        #pragma unroll
        for (int e = 0; e < NTILE; e++)
            #pragma unroll
            for (int c = 0; c < 4; c++)
                S[(e * 4 + c) * 32 + lane] = acc[e][c];
    }
    __syncthreads();

    // ---- Epilogue: warp 0 adds partner partials, scatters strict-upper triu ----
    if (kw == 0) {
        float* orow = out + (size_t)sample * NPAIR;
        #pragma unroll
        for (int e = 0; e < NTILE; e++)
            #pragma unroll
            for (int c = 0; c < 4; c++) {
                const float v = acc[e][c] + S[(e * 4 + c) * 32 + lane];
                const int i = MT[e] * 16 + g + ((c & 2) ? 8 : 0);
                const int j = NT[e] * 8 + 2 * t4 + (c & 1);
                if (i < j && j < N)
                    orow[i * (2 * N - 1 - i) / 2 + (j - i - 1)] = v;
            }
    }
}

extern "C" void kernel_launch(void* const* d_in, const int* in_sizes, int n_in,
                              void* d_out, int out_size)
{
    const float* dense = (const float*)d_in[0];
    const float* embs  = (const float*)d_in[1];
    float* out = (float*)d_out;
    dot_interaction_kernel<<<Bt, NTHR>>>(dense, embs, out);
}